// round 6
// baseline (speedup 1.0000x reference)
#include <cuda_runtime.h>

#define IMG_H 480
#define IMG_W 640
#define IMG_HW (IMG_H * IMG_W)
#define OCH 64
#define KK 25            // 5x5
#define WP 14            // u64 k-pairs per weight row (13 used + 1 zero pad), 112 B stride
#define TKX 128          // tile width in pixels
#define TKY 4            // tile height in pixels
#define SW 132           // smem tile row width  (TKX + 4)
#define SH 8             // smem tile rows       (TKY + 4)
#define THREADS 256
#define THRESH 1e-4f

// ---- packed f32x2 helpers (Blackwell FFMA2 path, PTX-only) ----
__device__ __forceinline__ unsigned long long ffma2(unsigned long long a,
                                                    unsigned long long b,
                                                    unsigned long long c) {
    unsigned long long d;
    asm("fma.rn.f32x2 %0, %1, %2, %3;" : "=l"(d) : "l"(a), "l"(b), "l"(c));
    return d;
}
__device__ __forceinline__ unsigned long long pack2(float lo, float hi) {
    unsigned long long d;
    asm("mov.b64 %0, {%1, %2};" : "=l"(d) : "f"(lo), "f"(hi));
    return d;
}
__device__ __forceinline__ float hfold(unsigned long long d) {   // lo + hi
    float lo, hi;
    asm("mov.b64 {%0, %1}, %2;" : "=f"(lo), "=f"(hi) : "l"(d));
    return lo + hi;
}

__global__ __launch_bounds__(THREADS, 3)
void normdepthconv_kernel(const float* __restrict__ x,
                          const float* __restrict__ wt,
                          float* __restrict__ out) {
    __shared__ float tile[SH * SW];                            // 4224 B
    __shared__ __align__(16) unsigned long long w2s[OCH * WP]; // 7168 B, {w2j,w2j+1} pairs

    const int b  = blockIdx.z;
    const int X0 = blockIdx.x * TKX;
    const int Y0 = blockIdx.y * TKY;
    const int tid = threadIdx.x;

    // ---- cooperative halo-tile load (zero-padded borders) ----
    const float* xb = x + (size_t)b * IMG_HW;
    for (int i = tid; i < SH * SW; i += THREADS) {
        int r = i / SW;
        int c = i - r * SW;
        int gy = Y0 - 2 + r;
        int gx = X0 - 2 + c;
        float v = 0.f;
        if (gy >= 0 && gy < IMG_H && gx >= 0 && gx < IMG_W) v = xb[gy * IMG_W + gx];
        tile[i] = v;
    }
    // ---- weights as k-pair u64s: {w[2j], w[2j+1]}, row padded to WP pairs ----
    for (int i = tid; i < OCH * WP; i += THREADS) {
        int o = i / WP;
        int j = i - o * WP;
        unsigned long long v;
        if (j < 12)       v = pack2(wt[o * KK + 2 * j], wt[o * KK + 2 * j + 1]);
        else if (j == 12) v = pack2(wt[o * KK + 24], 0.f);
        else              v = 0ull;
        w2s[i] = v;
    }
    __syncthreads();

    const int tx = tid & 63;     // 64 threads across x, 2 pixels each -> 128
    const int ty = tid >> 6;     // 4 rows
    const int c0 = 2 * tx;       // smem col of leftmost needed value (8B aligned)

    // ---- pass 1: box sums S and valid counts N for 2 pixels ----
    float S0 = 0.f, S1 = 0.f, N0 = 0.f, N1 = 0.f;
#pragma unroll
    for (int dy = 0; dy < 5; ++dy) {
        const float2* row = reinterpret_cast<const float2*>(&tile[(ty + dy) * SW + c0]);
        float2 p0 = row[0], p1 = row[1], p2 = row[2];
        float v[6] = {p0.x, p0.y, p1.x, p1.y, p2.x, p2.y};
#pragma unroll
        for (int kw = 0; kw < 5; ++kw) {
            S0 += v[kw];     N0 += (v[kw]     > THRESH) ? 1.f : 0.f;
            S1 += v[kw + 1]; N1 += (v[kw + 1] > THRESH) ? 1.f : 0.f;
        }
    }
    const float ref0 = S0 / (N0 + 1e-6f);
    const float ref1 = S1 / (N1 + 1e-6f);

    // ---- pass 2: per-pixel t packed along k: tpX[j] = {t[2j], t[2j+1]} ----
    unsigned long long tp0[13], tp1[13];
    float pv0, pv1;                                 // pending even-k values
#pragma unroll
    for (int dy = 0; dy < 5; ++dy) {
        const float2* row = reinterpret_cast<const float2*>(&tile[(ty + dy) * SW + c0]);
        float2 p0 = row[0], p1 = row[1], p2 = row[2];
        float v[6] = {p0.x, p0.y, p1.x, p1.y, p2.x, p2.y};
#pragma unroll
        for (int kw = 0; kw < 5; ++kw) {
            const int k = dy * 5 + kw;
            float t0 = (v[kw]     > THRESH) ? (ref0 - v[kw])     : 0.f;
            float t1 = (v[kw + 1] > THRESH) ? (ref1 - v[kw + 1]) : 0.f;
            if (k & 1) {
                tp0[k >> 1] = pack2(pv0, t0);
                tp1[k >> 1] = pack2(pv1, t1);
            } else {
                pv0 = t0; pv1 = t1;
            }
        }
    }
    tp0[12] = pack2(pv0, 0.f);   // k = 24
    tp1[12] = pack2(pv1, 0.f);

    // ---- 64-channel GEMV: LDS.128 = 4 distinct weights, o unrolled x2 ----
    float* outp = out + (size_t)b * OCH * IMG_HW + (size_t)(Y0 + ty) * IMG_W + (X0 + c0);
#pragma unroll 1
    for (int o = 0; o < OCH; o += 2) {
        const unsigned long long* wrA = &w2s[o * WP];
        const unsigned long long* wrB = &w2s[(o + 1) * WP];
        const ulonglong2* wA2 = reinterpret_cast<const ulonglong2*>(wrA);
        const ulonglong2* wB2 = reinterpret_cast<const ulonglong2*>(wrB);
        unsigned long long a0 = 0ull, a1 = 0ull;    // channel o,   px0/px1
        unsigned long long b0 = 0ull, b1 = 0ull;    // channel o+1, px0/px1
#pragma unroll
        for (int j = 0; j < 6; ++j) {               // k-pairs 2j, 2j+1 (0..11)
            ulonglong2 wA = wA2[j];
            ulonglong2 wB = wB2[j];
            unsigned long long u0 = tp0[2 * j],     u1 = tp1[2 * j];
            unsigned long long v0 = tp0[2 * j + 1], v1 = tp1[2 * j + 1];
            a0 = ffma2(wA.x, u0, a0);
            a1 = ffma2(wA.x, u1, a1);
            b0 = ffma2(wB.x, u0, b0);
            b1 = ffma2(wB.x, u1, b1);
            a0 = ffma2(wA.y, v0, a0);
            a1 = ffma2(wA.y, v1, a1);
            b0 = ffma2(wB.y, v0, b0);
            b1 = ffma2(wB.y, v1, b1);
        }
        {
            unsigned long long wA12 = wrA[12];      // {w24, 0}
            unsigned long long wB12 = wrB[12];
            a0 = ffma2(wA12, tp0[12], a0);
            a1 = ffma2(wA12, tp1[12], a1);
            b0 = ffma2(wB12, tp0[12], b0);
            b1 = ffma2(wB12, tp1[12], b1);
        }
        *reinterpret_cast<float2*>(outp)          = make_float2(hfold(a0), hfold(a1));
        *reinterpret_cast<float2*>(outp + IMG_HW) = make_float2(hfold(b0), hfold(b1));
        outp += 2 * IMG_HW;                         // pointer increment, no per-o IMAD
    }
}

extern "C" void kernel_launch(void* const* d_in, const int* in_sizes, int n_in,
                              void* d_out, int out_size) {
    const float* x = (const float*)d_in[0];
    const float* w = (const float*)d_in[1];
    if (n_in >= 2 && in_sizes[0] == OCH * KK) {   // defensive input-order check
        x = (const float*)d_in[1];
        w = (const float*)d_in[0];
    }
    dim3 grid(IMG_W / TKX, IMG_H / TKY, 8);   // 5 x 120 x 8 = 4800 CTAs
    normdepthconv_kernel<<<grid, THREADS>>>(x, w, (float*)d_out);
}

// round 7
// speedup vs baseline: 1.2487x; 1.2487x over previous
#include <cuda_runtime.h>

#define IMG_H 480
#define IMG_W 640
#define IMG_HW (IMG_H * IMG_W)
#define OCH 64
#define KK 25            // 5x5
#define TKX 128          // tile width in pixels
#define TKY 8            // tile height in pixels
#define SW 132           // smem tile row width  (TKX + 4)
#define SH 12            // smem tile rows       (TKY + 4)
#define THREADS 256
#define THRESH 1e-4f

// {w,w} duplicated weight pairs in constant bank -> LDCU/uniform port, not LSU
__constant__ unsigned long long CW2[OCH * KK];          // 12800 B
__device__ unsigned long long g_wpair[OCH * KK];        // prep scratch

// ---- packed f32x2 helpers (Blackwell FFMA2 path, PTX-only) ----
__device__ __forceinline__ unsigned long long ffma2(unsigned long long a,
                                                    unsigned long long b,
                                                    unsigned long long c) {
    unsigned long long d;
    asm("fma.rn.f32x2 %0, %1, %2, %3;" : "=l"(d) : "l"(a), "l"(b), "l"(c));
    return d;
}
__device__ __forceinline__ unsigned long long pack2(float lo, float hi) {
    unsigned long long d;
    asm("mov.b64 %0, {%1, %2};" : "=l"(d) : "f"(lo), "f"(hi));
    return d;
}
__device__ __forceinline__ void unpack2(unsigned long long d, float& lo, float& hi) {
    asm("mov.b64 {%0, %1}, %2;" : "=f"(lo), "=f"(hi) : "l"(d));
}

__global__ void prep_weights(const float* __restrict__ wt) {
    int i = blockIdx.x * blockDim.x + threadIdx.x;
    if (i < OCH * KK) {
        float w = wt[i];
        g_wpair[i] = pack2(w, w);
    }
}

__global__ __launch_bounds__(THREADS, 2)
void normdepthconv_kernel(const float* __restrict__ x,
                          float* __restrict__ out) {
    __shared__ float tile[SH * SW];                 // 6336 B (only smem use)

    const int b  = blockIdx.z;
    const int X0 = blockIdx.x * TKX;
    const int Y0 = blockIdx.y * TKY;
    const int tid = threadIdx.x;

    // ---- cooperative halo-tile load (zero-padded borders) ----
    const float* xb = x + (size_t)b * IMG_HW;
    for (int i = tid; i < SH * SW; i += THREADS) {
        int r = i / SW;
        int c = i - r * SW;
        int gy = Y0 - 2 + r;
        int gx = X0 - 2 + c;
        float v = 0.f;
        if (gy >= 0 && gy < IMG_H && gx >= 0 && gx < IMG_W) v = xb[gy * IMG_W + gx];
        tile[i] = v;
    }
    __syncthreads();

    const int tx = tid & 31;     // 32 threads across x, 4 pixels each -> 128
    const int ty = tid >> 5;     // 8 rows
    const int c0 = 4 * tx;       // smem col of leftmost needed value (16B aligned)

    // ---- pass 1: box sums S and valid counts N for 4 pixels ----
    float S0 = 0.f, S1 = 0.f, S2 = 0.f, S3 = 0.f;
    float N0 = 0.f, N1 = 0.f, N2 = 0.f, N3 = 0.f;
#pragma unroll
    for (int dy = 0; dy < 5; ++dy) {
        const float4* row = reinterpret_cast<const float4*>(&tile[(ty + dy) * SW + c0]);
        float4 lo = row[0];
        float4 hi = row[1];
        float v[8] = {lo.x, lo.y, lo.z, lo.w, hi.x, hi.y, hi.z, hi.w};
#pragma unroll
        for (int kw = 0; kw < 5; ++kw) {
            S0 += v[kw];     N0 += (v[kw]     > THRESH) ? 1.f : 0.f;
            S1 += v[kw + 1]; N1 += (v[kw + 1] > THRESH) ? 1.f : 0.f;
            S2 += v[kw + 2]; N2 += (v[kw + 2] > THRESH) ? 1.f : 0.f;
            S3 += v[kw + 3]; N3 += (v[kw + 3] > THRESH) ? 1.f : 0.f;
        }
    }
    const float ref0 = S0 / (N0 + 1e-6f);
    const float ref1 = S1 / (N1 + 1e-6f);
    const float ref2 = S2 / (N2 + 1e-6f);
    const float ref3 = S3 / (N3 + 1e-6f);

    // ---- pass 2: packed t-vectors  t[k] = mask * (ref - v) ----
    unsigned long long ta[KK];   // pixels 0,1
    unsigned long long tb[KK];   // pixels 2,3
#pragma unroll
    for (int dy = 0; dy < 5; ++dy) {
        const float4* row = reinterpret_cast<const float4*>(&tile[(ty + dy) * SW + c0]);
        float4 lo = row[0];
        float4 hi = row[1];
        float v[8] = {lo.x, lo.y, lo.z, lo.w, hi.x, hi.y, hi.z, hi.w};
#pragma unroll
        for (int kw = 0; kw < 5; ++kw) {
            const int k = dy * 5 + kw;
            float t0 = (v[kw]     > THRESH) ? (ref0 - v[kw])     : 0.f;
            float t1 = (v[kw + 1] > THRESH) ? (ref1 - v[kw + 1]) : 0.f;
            float t2 = (v[kw + 2] > THRESH) ? (ref2 - v[kw + 2]) : 0.f;
            float t3 = (v[kw + 3] > THRESH) ? (ref3 - v[kw + 3]) : 0.f;
            ta[k] = pack2(t0, t1);
            tb[k] = pack2(t2, t3);
        }
    }

    // ---- 64-channel packed GEMV, weights via constant/uniform port ----
    float* outp = out + (size_t)b * OCH * IMG_HW + (size_t)(Y0 + ty) * IMG_W + (X0 + c0);
#pragma unroll 1
    for (int o = 0; o < OCH; ++o) {
        const unsigned long long* wrow = &CW2[o * KK];
        unsigned long long accA = 0ull;   // {0.f, 0.f}
        unsigned long long accB = 0ull;
#pragma unroll
        for (int k = 0; k < KK; ++k) {
            unsigned long long w = wrow[k];      // LDCU (uniform const port)
            accA = ffma2(w, ta[k], accA);
            accB = ffma2(w, tb[k], accB);
        }
        float o0, o1, o2, o3;
        unpack2(accA, o0, o1);
        unpack2(accB, o2, o3);
        *reinterpret_cast<float4*>(outp) = make_float4(o0, o1, o2, o3);
        outp += IMG_HW;                           // pointer bump, no per-o IMAD
    }
}

extern "C" void kernel_launch(void* const* d_in, const int* in_sizes, int n_in,
                              void* d_out, int out_size) {
    const float* x = (const float*)d_in[0];
    const float* w = (const float*)d_in[1];
    if (n_in >= 2 && in_sizes[0] == OCH * KK) {   // defensive input-order check
        x = (const float*)d_in[1];
        w = (const float*)d_in[0];
    }

    // 1) build {w,w} pairs in device scratch
    prep_weights<<<(OCH * KK + 255) / 256, 256>>>(w);
    // 2) copy pairs into the constant bank (D2D memcpy node, graph-capturable)
    void* src = nullptr;
    cudaGetSymbolAddress(&src, g_wpair);
    cudaMemcpyToSymbolAsync(CW2, src, OCH * KK * sizeof(unsigned long long), 0,
                            cudaMemcpyDeviceToDevice);
    // 3) main kernel
    dim3 grid(IMG_W / TKX, IMG_H / TKY, 8);   // 5 x 60 x 8 = 2400 CTAs
    normdepthconv_kernel<<<grid, THREADS>>>(x, (float*)d_out);
}